// round 14
// baseline (speedup 1.0000x reference)
#include <cuda_runtime.h>

// SMFNet B=2,N=8192,D=64,DV=64,M=3 — chord mask = diag + superdiag(wrap).
// out[i] = w0 V0[i] + w1 V0[i+1] + w2 V0[i+2] + w3 V0[i+3]   (wrap)
//   V0 = X@Wg + bg
//   Am_j = X[j]·Wf[m][:,j] + bf[m][j],  Cm_j = X[j]·Wf[m][:,j+1] + bf[m][j+1]
// R14: fused, TROWS=32 one batch per CTA (512 CTAs), GEMM retiled to
// 1 row x 8 cols per thread (8 instr / 16 MACs per d), Wg in smem,
// column-shared A/C on warps 0-3, extra GEMM rows on warp 7.

#define Nc   8192
#define Dc   64
#define TROWS 32
#define XSL   36          // staged row slots (35 used: 32 + 3 halo)
#define PAD   68          // float4-aligned row stride (272B)
#define ACW   36
#define NTHREADS 256

typedef unsigned long long u64;

// smem (floats)
#define OFF_XS  0                     // XSL*PAD = 2448
#define OFF_VS  (OFF_XS + XSL*PAD)    // 2448   (byte 9792, 16B-aligned)
#define OFF_WG  (OFF_VS + XSL*PAD)    // 4096   (byte 19584, 16B-aligned)
#define OFF_AS  (OFF_WG + 64*64)      // 108
#define OFF_CS  (OFF_AS + ACW*3)      // 108
#define SMEM_FLOATS (OFF_CS + ACW*3)
#define SMEM_BYTES  (SMEM_FLOATS * 4)

__device__ __forceinline__ u64 pack2(float x, float y) {
    u64 r;
    asm("mov.b64 %0, {%1, %2};" : "=l"(r) : "f"(x), "f"(y));
    return r;
}
__device__ __forceinline__ void fma2(u64& d, u64 a, u64 b) {
    asm("fma.rn.f32x2 %0, %1, %2, %3;" : "=l"(d) : "l"(a), "l"(b), "l"(d));
}

__global__ __launch_bounds__(NTHREADS, 4)
void smf_fused_kernel(const float* __restrict__ X,
                      const float* __restrict__ Wg,
                      const float* __restrict__ bg,
                      const float* __restrict__ Wf,
                      const float* __restrict__ bf,
                      float* __restrict__ out)
{
    extern __shared__ float sm[];
    float* Xs  = sm + OFF_XS;   // [XSL][PAD]
    float* Vs  = sm + OFF_VS;   // [XSL][PAD]
    float* Wgs = sm + OFF_WG;   // [64][64]
    float* As  = sm + OFF_AS;   // [m*ACW + j]
    float* Cs  = sm + OFF_CS;

    const int t  = threadIdx.x;
    const int b  = blockIdx.y;
    const int r0 = blockIdx.x * TROWS;

    // ---- Phase A: stage X rows r0..r0+34 (wrap) + Wg ----
    {
        const float4* Xb4 = reinterpret_cast<const float4*>(X + (size_t)b * Nc * Dc);
        #pragma unroll
        for (int idx = t; idx < 35 * 16; idx += NTHREADS) {
            int rs = idx >> 4, q = idx & 15;
            int gi = (r0 + rs) & (Nc - 1);
            *reinterpret_cast<float4*>(&Xs[rs * PAD + q * 4]) = __ldg(Xb4 + gi * 16 + q);
        }
        const float4* Wg4 = reinterpret_cast<const float4*>(Wg);
        #pragma unroll
        for (int idx = t; idx < 64 * 16; idx += NTHREADS)
            *reinterpret_cast<float4*>(&Wgs[idx * 4]) = __ldg(Wg4 + idx);
    }
    __syncthreads();

    // ---- Phase B1 (warps 0-3): column-shared A/C dots, 105 tasks ----
    // Column gi = r0+c serves A[c] (vs X[c]) and C[c-1] (vs X[c-1]).
    if (t < 105) {
        const int c = t % 35;
        const int m = t / 35;
        const int gi  = (r0 + c) & (Nc - 1);
        const int cm1 = (c == 0) ? 0 : (c - 1);
        const float* wp = Wf + (size_t)m * Dc * Nc + gi;
        const float* xA = &Xs[c   * PAD];
        const float* xC = &Xs[cm1 * PAD];
        float aA0 = 0.f, aA1 = 0.f, aC0 = 0.f, aC1 = 0.f;
        #pragma unroll 16
        for (int d = 0; d < Dc; d += 2) {
            float w0 = __ldg(wp + (size_t)d * Nc);
            float w1 = __ldg(wp + (size_t)(d + 1) * Nc);
            aA0 = fmaf(xA[d],     w0, aA0);
            aA1 = fmaf(xA[d + 1], w1, aA1);
            aC0 = fmaf(xC[d],     w0, aC0);
            aC1 = fmaf(xC[d + 1], w1, aC1);
        }
        const float bfv = __ldg(bf + m * Nc + gi);
        if (c < 34) As[m * ACW + c] = aA0 + aA1 + bfv;
        if (c >= 1) Cs[m * ACW + (c - 1)] = aC0 + aC1 + bfv;
    }

    // ---- Phase B2: GEMM V0 = X@Wg + bg, 35 rows ----
    // thread: row rg = t>>3 (0..31), cols [8cg, 8cg+8); warp 7 (rg>=28)
    // additionally computes row rg+4 (32..35 slots; 35 used).
    {
        const int cg = t & 7;
        const int rg = t >> 3;
        const int e0 = cg * 8;
        const bool ex = (rg >= 28);
        const int r2 = rg + 4;              // 32..35 for warp 7

        float4 bq0 = __ldg(reinterpret_cast<const float4*>(bg + e0));
        float4 bq1 = __ldg(reinterpret_cast<const float4*>(bg + e0 + 4));
        u64 a0 = pack2(bq0.x, bq0.y), a1 = pack2(bq0.z, bq0.w);
        u64 a2 = pack2(bq1.x, bq1.y), a3 = pack2(bq1.z, bq1.w);
        u64 c0 = a0, c1 = a1, c2 = a2, c3 = a3;

        const float* x0p = &Xs[rg * PAD];
        const float* x1p = &Xs[r2 * PAD];
        const ulonglong2* w2p = reinterpret_cast<const ulonglong2*>(Wgs) + cg * 2;

        #pragma unroll 8
        for (int d = 0; d < Dc; d++) {
            ulonglong2 wA = w2p[d * 16];
            ulonglong2 wB = w2p[d * 16 + 1];
            float x0 = x0p[d];
            u64 xx0 = pack2(x0, x0);
            fma2(a0, xx0, wA.x);  fma2(a1, xx0, wA.y);
            fma2(a2, xx0, wB.x);  fma2(a3, xx0, wB.y);
            if (ex) {
                float x1 = x1p[d];
                u64 xx1 = pack2(x1, x1);
                fma2(c0, xx1, wA.x);  fma2(c1, xx1, wA.y);
                fma2(c2, xx1, wB.x);  fma2(c3, xx1, wB.y);
            }
        }
        ulonglong2* v0 = reinterpret_cast<ulonglong2*>(&Vs[rg * PAD + e0]);
        v0[0] = make_ulonglong2(a0, a1);
        v0[1] = make_ulonglong2(a2, a3);
        if (ex) {
            ulonglong2* v1 = reinterpret_cast<ulonglong2*>(&Vs[r2 * PAD + e0]);
            v1[0] = make_ulonglong2(c0, c1);
            v1[1] = make_ulonglong2(c2, c3);
        }
    }
    __syncthreads();

    // ---- Phase C: inline weights + 4-tap combine + store (512 tasks) ----
    #pragma unroll
    for (int k = 0; k < 2; k++) {
        const int task = t + k * NTHREADS;
        const int jr = task >> 4;
        const int e0 = (task & 15) * 4;

        float A1i = As[0 * ACW + jr], A1i1 = As[0 * ACW + jr + 1], A1i2 = As[0 * ACW + jr + 2];
        float C1i = Cs[0 * ACW + jr], C1i1 = Cs[0 * ACW + jr + 1], C1i2 = Cs[0 * ACW + jr + 2];
        float A2i = As[1 * ACW + jr], A2i1 = As[1 * ACW + jr + 1];
        float C2i = Cs[1 * ACW + jr], C2i1 = Cs[1 * ACW + jr + 1];
        float A3  = As[2 * ACW + jr], C3   = Cs[2 * ACW + jr];
        float w0 = A3 * A2i * A1i;
        float w1 = A3 * (A2i * C1i + C2i * A1i1) + C3 * A2i1 * A1i1;
        float w2 = A3 * C2i * C1i1 + C3 * (A2i1 * C1i1 + C2i1 * A1i2);
        float w3 = C3 * C2i1 * C1i2;

        const float* vb = &Vs[jr * PAD + e0];
        float4 p0 = *reinterpret_cast<const float4*>(vb);
        float4 p1 = *reinterpret_cast<const float4*>(vb + PAD);
        float4 p2 = *reinterpret_cast<const float4*>(vb + 2 * PAD);
        float4 p3 = *reinterpret_cast<const float4*>(vb + 3 * PAD);

        float4 o;
        o.x = w0 * p0.x + w1 * p1.x + w2 * p2.x + w3 * p3.x;
        o.y = w0 * p0.y + w1 * p1.y + w2 * p2.y + w3 * p3.y;
        o.z = w0 * p0.z + w1 * p1.z + w2 * p2.z + w3 * p3.z;
        o.w = w0 * p0.w + w1 * p1.w + w2 * p2.w + w3 * p3.w;

        const int gi = r0 + jr;     // <= 8191+31, but jr<=31 and r0<=8160 -> no wrap
        *reinterpret_cast<float4*>(&out[((size_t)b * Nc + gi) * 64 + e0]) = o;
    }
}

extern "C" void kernel_launch(void* const* d_in, const int* in_sizes, int n_in,
                              void* d_out, int out_size)
{
    const float* X  = (const float*)d_in[0];   // (2, 8192, 64)
    const float* Wg = (const float*)d_in[1];   // (64, 64)
    const float* bg = (const float*)d_in[2];   // (64,)
    const float* Wf = (const float*)d_in[3];   // (3, 64, 8192)
    const float* bf = (const float*)d_in[4];   // (3, 8192)
    float* out = (float*)d_out;                // (2, 8192, 64)

    cudaFuncSetAttribute(smf_fused_kernel,
                         cudaFuncAttributeMaxDynamicSharedMemorySize, SMEM_BYTES);

    dim3 grid(Nc / TROWS, 2);                  // (256, 2) = 512 CTAs
    smf_fused_kernel<<<grid, NTHREADS, SMEM_BYTES>>>(X, Wg, bg, Wf, bf, out);
}

// round 16
// speedup vs baseline: 1.6212x; 1.6212x over previous
#include <cuda_runtime.h>

// SMFNet B=2,N=8192,D=64,DV=64,M=3 — chord mask = diag + superdiag(wrap).
// out[i] = w0 V0[i] + w1 V0[i+1] + w2 V0[i+2] + w3 V0[i+3]   (wrap)
//   V0 = X@Wg + bg
//   Am_j = X[j]·Wf[m][:,j] + bf[m][j],  Cm_j = X[j]·Wf[m][:,j+1] + bf[m][j+1]
// R16 = R15 with the x-float4 indexing fix (x0q[h], not x0q[h*(PAD/4)]).
// (a) A/C dots split 2-way over d (228 tasks, smem partials),
// (b) GEMM x loaded as float4 (1 LDS.128 per 4 d per row).

#define Bc   2
#define Nc   8192
#define Dc   64
#define TROWS 16           // output rows per CTA  -> 512 CTAs
#define XR    19           // staged rows per batch (TROWS + 3 halo)
#define RS    (2*XR)       // 38 row-slots
#define PAD   68           // float4-aligned row stride (272B)
#define ACW   20
#define NTHREADS 256

typedef unsigned long long u64;

// smem (floats)
#define OFF_XS  0                      // RS*PAD = 2584
#define OFF_VS  (OFF_XS + RS*PAD)      // 2584 (byte 10336, 16B-aligned)
#define OFF_AP  (OFF_VS + RS*PAD)      // 2*120
#define OFF_CP  (OFF_AP + 2*6*ACW)     // 2*120
#define SMEM_FLOATS (OFF_CP + 2*6*ACW)
#define SMEM_BYTES  (SMEM_FLOATS * 4)

__device__ __forceinline__ u64 pack2(float x, float y) {
    u64 r;
    asm("mov.b64 %0, {%1, %2};" : "=l"(r) : "f"(x), "f"(y));
    return r;
}
__device__ __forceinline__ void fma2(u64& d, u64 a, u64 b) {
    asm("fma.rn.f32x2 %0, %1, %2, %3;" : "=l"(d) : "l"(a), "l"(b), "l"(d));
}

__global__ __launch_bounds__(NTHREADS, 4)
void smf_fused_kernel(const float* __restrict__ X,
                      const float* __restrict__ Wg,
                      const float* __restrict__ bg,
                      const float* __restrict__ Wf,
                      const float* __restrict__ bf,
                      float* __restrict__ out)
{
    extern __shared__ float sm[];
    float* Xs  = sm + OFF_XS;   // [RS][PAD], rs = b*XR + j
    float* Vs  = sm + OFF_VS;   // [RS][PAD]
    float* Ap  = sm + OFF_AP;   // [2][6*ACW]  d-half partials
    float* Cp  = sm + OFF_CP;   // [2][6*ACW]

    const int t  = threadIdx.x;
    const int r0 = blockIdx.x * TROWS;

    // ---- Phase A: stage X rows r0..r0+18 (wrap) for both batches ----
    {
        const float4* X4 = reinterpret_cast<const float4*>(X);
        #pragma unroll
        for (int idx = t; idx < RS * 16; idx += NTHREADS) {
            int rs = idx >> 4, q = idx & 15;
            int b  = rs >= XR;
            int j  = rs - b * XR;
            int gi = (r0 + j) & (Nc - 1);
            *reinterpret_cast<float4*>(&Xs[rs * PAD + q * 4]) =
                __ldg(X4 + ((size_t)b * Nc + gi) * 16 + q);
        }
    }
    __syncthreads();

    // ---- Phase B1: column-shared A/C dots, d-split 2-way. 228 tasks. ----
    // task = (half, s): s -> (c, m, b); column gi=r0+c serves A[c] and C[c-1].
    if (t < 228) {
        const int half = t >= 114;
        const int s = t - 114 * half;
        const int c = s % 19;
        const int g = s / 19;           // 0..5
        const int m = g % 3;
        const int b = g / 3;
        const int gi  = (r0 + c) & (Nc - 1);
        const int cm1 = (c == 0) ? 0 : (c - 1);
        const int d0  = half * 32;
        const float* wp = Wf + (size_t)m * Dc * Nc + (size_t)d0 * Nc + gi;
        const float* xA = &Xs[(b * XR + c)   * PAD + d0];
        const float* xC = &Xs[(b * XR + cm1) * PAD + d0];
        float aA0 = 0.f, aA1 = 0.f, aC0 = 0.f, aC1 = 0.f;
        #pragma unroll
        for (int d = 0; d < 32; d += 2) {
            float w0 = __ldg(wp + (size_t)d * Nc);
            float w1 = __ldg(wp + (size_t)(d + 1) * Nc);
            aA0 = fmaf(xA[d],     w0, aA0);
            aA1 = fmaf(xA[d + 1], w1, aA1);
            aC0 = fmaf(xC[d],     w0, aC0);
            aC1 = fmaf(xC[d + 1], w1, aC1);
        }
        const float bfv = half ? 0.f : __ldg(bf + m * Nc + gi);
        const int si = (b * 3 + m) * ACW;
        if (c < 18) Ap[half * 120 + si + c] = aA0 + aA1 + bfv;
        if (c >= 1) Cp[half * 120 + si + (c - 1)] = aC0 + aC1 + bfv;
    }

    // ---- Phase B2: GEMM V0 = X@Wg + bg for all 38 row-slots ----
    // thread: col quad e0 = 4*(t&15); rows rsb, rsb+16, (+32 if rsb<6).
    // x fetched as float4 per 4 d; Wg via LDG.128 (L1-resident).
    {
        const int e0  = (t & 15) * 4;
        const int rsb = t >> 4;
        const bool has3 = (rsb < RS - 32);     // warp-uniform

        float4 bgq = __ldg(reinterpret_cast<const float4*>(bg + e0));
        u64 a0_01 = pack2(bgq.x, bgq.y), a0_23 = pack2(bgq.z, bgq.w);
        u64 a1_01 = a0_01, a1_23 = a0_23;
        u64 a2_01 = a0_01, a2_23 = a0_23;

        const float4* x0q = reinterpret_cast<const float4*>(&Xs[rsb * PAD]);
        const float4* x1q = reinterpret_cast<const float4*>(&Xs[(rsb + 16) * PAD]);
        const float4* x2q = reinterpret_cast<const float4*>(&Xs[(has3 ? rsb + 32 : rsb) * PAD]);

        #pragma unroll 4
        for (int h = 0; h < Dc / 4; h++) {
            float4 xa = x0q[h];              // floats 4h..4h+3 of row rsb
            float4 xb = x1q[h];
            float4 xc = has3 ? x2q[h] : xa;
            const float* xaf = reinterpret_cast<const float*>(&xa);
            const float* xbf = reinterpret_cast<const float*>(&xb);
            const float* xcf = reinterpret_cast<const float*>(&xc);
            #pragma unroll
            for (int k = 0; k < 4; k++) {
                const int d = 4 * h + k;
                float4 wv = __ldg(reinterpret_cast<const float4*>(Wg + d * 64 + e0));
                u64 w01 = pack2(wv.x, wv.y);
                u64 w23 = pack2(wv.z, wv.w);
                u64 xx0 = pack2(xaf[k], xaf[k]);
                u64 xx1 = pack2(xbf[k], xbf[k]);
                fma2(a0_01, xx0, w01);  fma2(a0_23, xx0, w23);
                fma2(a1_01, xx1, w01);  fma2(a1_23, xx1, w23);
                if (has3) {
                    u64 xx2 = pack2(xcf[k], xcf[k]);
                    fma2(a2_01, xx2, w01);  fma2(a2_23, xx2, w23);
                }
            }
        }
        *reinterpret_cast<ulonglong2*>(&Vs[rsb * PAD + e0]) =
            make_ulonglong2(a0_01, a0_23);
        *reinterpret_cast<ulonglong2*>(&Vs[(rsb + 16) * PAD + e0]) =
            make_ulonglong2(a1_01, a1_23);
        if (has3)
            *reinterpret_cast<ulonglong2*>(&Vs[(rsb + 32) * PAD + e0]) =
                make_ulonglong2(a2_01, a2_23);
    }
    __syncthreads();

    // ---- Phase C: weights from partials + 4-tap combine + store ----
    {
        const int e0 = (t & 15) * 4;
        const int jr = t >> 4;
        #pragma unroll
        for (int b = 0; b < Bc; b++) {
            const int s0 = (b * 3 + 0) * ACW;
            const int s1 = (b * 3 + 1) * ACW;
            const int s2 = (b * 3 + 2) * ACW;
            float A1i  = Ap[s0 + jr]     + Ap[120 + s0 + jr];
            float A1i1 = Ap[s0 + jr + 1] + Ap[120 + s0 + jr + 1];
            float A1i2 = Ap[s0 + jr + 2] + Ap[120 + s0 + jr + 2];
            float C1i  = Cp[s0 + jr]     + Cp[120 + s0 + jr];
            float C1i1 = Cp[s0 + jr + 1] + Cp[120 + s0 + jr + 1];
            float C1i2 = Cp[s0 + jr + 2] + Cp[120 + s0 + jr + 2];
            float A2i  = Ap[s1 + jr]     + Ap[120 + s1 + jr];
            float A2i1 = Ap[s1 + jr + 1] + Ap[120 + s1 + jr + 1];
            float C2i  = Cp[s1 + jr]     + Cp[120 + s1 + jr];
            float C2i1 = Cp[s1 + jr + 1] + Cp[120 + s1 + jr + 1];
            float A3   = Ap[s2 + jr]     + Ap[120 + s2 + jr];
            float C3   = Cp[s2 + jr]     + Cp[120 + s2 + jr];

            float w0 = A3 * A2i * A1i;
            float w1 = A3 * (A2i * C1i + C2i * A1i1) + C3 * A2i1 * A1i1;
            float w2 = A3 * C2i * C1i1 + C3 * (A2i1 * C1i1 + C2i1 * A1i2);
            float w3 = C3 * C2i1 * C1i2;

            const float* vb = &Vs[(b * XR + jr) * PAD + e0];
            float4 p0 = *reinterpret_cast<const float4*>(vb);
            float4 p1 = *reinterpret_cast<const float4*>(vb + PAD);
            float4 p2 = *reinterpret_cast<const float4*>(vb + 2 * PAD);
            float4 p3 = *reinterpret_cast<const float4*>(vb + 3 * PAD);

            float4 o;
            o.x = w0 * p0.x + w1 * p1.x + w2 * p2.x + w3 * p3.x;
            o.y = w0 * p0.y + w1 * p1.y + w2 * p2.y + w3 * p3.y;
            o.z = w0 * p0.z + w1 * p1.z + w2 * p2.z + w3 * p3.z;
            o.w = w0 * p0.w + w1 * p1.w + w2 * p2.w + w3 * p3.w;

            const int gi = r0 + jr;
            *reinterpret_cast<float4*>(&out[((size_t)b * Nc + gi) * 64 + e0]) = o;
        }
    }
}

extern "C" void kernel_launch(void* const* d_in, const int* in_sizes, int n_in,
                              void* d_out, int out_size)
{
    const float* X  = (const float*)d_in[0];   // (2, 8192, 64)
    const float* Wg = (const float*)d_in[1];   // (64, 64)
    const float* bg = (const float*)d_in[2];   // (64,)
    const float* Wf = (const float*)d_in[3];   // (3, 64, 8192)
    const float* bf = (const float*)d_in[4];   // (3, 8192)
    float* out = (float*)d_out;                // (2, 8192, 64)

    cudaFuncSetAttribute(smf_fused_kernel,
                         cudaFuncAttributeMaxDynamicSharedMemorySize, SMEM_BYTES);

    dim3 grid(Nc / TROWS, 1);                  // 512 CTAs
    smf_fused_kernel<<<grid, NTHREADS, SMEM_BYTES>>>(X, Wg, bg, Wf, bf, out);
}